// round 14
// baseline (speedup 1.0000x reference)
#include <cuda_runtime.h>

#define B_ 512
#define L_ 100
#define E_ 50
#define D_ 512
#define DT 128
#define NP 56          // padded l-pairs for k5 weights
#define BLD ((size_t)B_ * L_ * D_)
#define NEGF -9000000000000000.0f

typedef unsigned long long ull;

// ---- scratch ----
__device__ float g_EDGE[(size_t)B_ * E_ * D_];     // edge feats (52 MB)
__device__ float2 g_ATTEP[(size_t)B_ * L_ * 28];   // att_edge, e-pair packed [b][l][pair]
__device__ float2 g_ATTNP[(size_t)B_ * E_ * NP];   // att_node, l-pair packed [b][e][pair]
__device__ float g_S[B_ * L_];                     // leaky(c0 + x.w_an)
__device__ float g_U[B_ * L_];                     // x.w_a2n
__device__ float g_wan[D_], g_wa2n[D_], g_w3e[D_];
__device__ float g_c0;

__device__ __forceinline__ float leaky(float x) { return x >= 0.f ? x : 0.2f * x; }

__device__ __forceinline__ ull fma2(ull a, ull b, ull c) {
    ull d;
    asm("fma.rn.f32x2 %0, %1, %2, %3;" : "=l"(d) : "l"(a), "l"(b), "l"(c));
    return d;
}
__device__ __forceinline__ ull dup2(float x) {
    ull d;
    asm("mov.b64 %0, {%1, %1};" : "=l"(d) : "f"(x));
    return d;
}
__device__ __forceinline__ float lo32(ull v) { return ((float2*)&v)->x; }
__device__ __forceinline__ float hi32(ull v) { return ((float2*)&v)->y; }

// ---- K0: fold W2/W3 into vectors (coalesced warp-per-row)
__global__ void k0(const float* __restrict__ W2, const float* __restrict__ W3,
                   const float* __restrict__ ctx, const float* __restrict__ a,
                   const float* __restrict__ a2) {
    int which = blockIdx.x;   // 4 blocks, 512 threads
    int t = threadIdx.x;
    if (which < 3) {
        const float* M = (which == 2) ? W3 : W2;
        const float* vec = (which == 0) ? (a + D_) : (which == 1 ? a2 : (a2 + D_));
        float* dst = (which == 0) ? g_wan : (which == 1 ? g_wa2n : g_w3e);
        __shared__ float vs[D_];
        vs[t] = vec[t];
        __syncthreads();
        int w = t >> 5, lane = t & 31;   // 16 warps
        for (int d = w; d < D_; d += 16) {
            const float4* row = (const float4*)(M + (size_t)d * D_);
            float s = 0.f;
            #pragma unroll
            for (int i = 0; i < 4; i++) {
                float4 mv = row[lane + 32 * i];
                float4 vv = *(const float4*)&vs[(lane + 32 * i) * 4];
                s += mv.x * vv.x + mv.y * vv.y + mv.z * vv.z + mv.w * vv.w;
            }
            for (int off = 16; off; off >>= 1) s += __shfl_xor_sync(0xffffffffu, s, off);
            if (lane == 0) dst[d] = s;
        }
    } else {
        __shared__ float sh[512];
        sh[t] = ctx[t] * a[t];
        __syncthreads();
        for (int o = 256; o > 0; o >>= 1) { if (t < o) sh[t] += sh[t + o]; __syncthreads(); }
        if (t == 0) g_c0 = sh[0];
    }
}

// ---- K1: warp-per-row dots from emb1 -> g_S, g_U
__global__ void k1(const int* __restrict__ inputs, const float* __restrict__ emb1) {
    int w = threadIdx.x >> 5, lane = threadIdx.x & 31;
    int bl = blockIdx.x * 8 + w;               // grid 6400 x 8 warps = 51200 rows
    size_t nid = (size_t)inputs[bl];
    const float4* r1 = (const float4*)(emb1 + nid * D_);

    float dan = 0.f, da2 = 0.f;
    #pragma unroll
    for (int i = 0; i < 4; i++) {
        int idx = lane + 32 * i;
        float4 v = r1[idx];
        float4 wa = ((const float4*)g_wan)[idx];
        float4 wb = ((const float4*)g_wa2n)[idx];
        dan += v.x * wa.x + v.y * wa.y + v.z * wa.z + v.w * wa.w;
        da2 += v.x * wb.x + v.y * wb.y + v.z * wb.z + v.w * wb.w;
    }
    for (int off = 16; off; off >>= 1) {
        dan += __shfl_xor_sync(0xffffffffu, dan, off);
        da2 += __shfl_xor_sync(0xffffffffu, da2, off);
    }
    if (lane == 0) {
        g_S[bl] = leaky(g_c0 + dan);
        g_U[bl] = da2;
    }
}

// ---- K2: att_edge softmax over l, written e-pair-packed: ATTEP[b][l][e>>1].{x,y}
__global__ void k2(const int* __restrict__ HT) {
    int b = blockIdx.x;
    __shared__ float s[L_];
    int t = threadIdx.x;   // 256
    if (t < L_) s[t] = g_S[b * L_ + t];
    for (int idx = t; idx < L_ * 3; idx += 256) {
        int l = idx / 3, p = 25 + idx % 3;
        g_ATTEP[(size_t)b * L_ * 28 + l * 28 + p] = make_float2(0.f, 0.f);
    }
    __syncthreads();
    float* op = (float*)(g_ATTEP + (size_t)b * L_ * 28);
    int w = t >> 5, lane = t & 31;
    for (int e = w; e < E_; e += 8) {
        const int* m = HT + ((size_t)b * E_ + e) * L_;
        float vals[4];
        float mx = -3.4e38f;
        #pragma unroll
        for (int k = 0; k < 4; k++) {
            int l = lane + 32 * k;
            float v = -3.4e38f;
            if (l < L_) v = (m[l] > 0) ? s[l] : NEGF;
            vals[k] = v;
            mx = fmaxf(mx, v);
        }
        for (int off = 16; off; off >>= 1) mx = fmaxf(mx, __shfl_xor_sync(0xffffffffu, mx, off));
        float sum = 0.f;
        #pragma unroll
        for (int k = 0; k < 4; k++) {
            int l = lane + 32 * k;
            float ev = 0.f;
            if (l < L_) ev = expf(vals[k] - mx);
            vals[k] = ev;
            sum += ev;
        }
        for (int off = 16; off; off >>= 1) sum += __shfl_xor_sync(0xffffffffu, sum, off);
        float inv = 1.f / sum;
        #pragma unroll
        for (int k = 0; k < 4; k++) {
            int l = lane + 32 * k;
            if (l < L_) op[(l * 28 + (e >> 1)) * 2 + (e & 1)] = vals[k] * inv;
        }
    }
}

// ---- K3: edge[b,e,:] = sum_l attE[b,e,l] * emb1[inputs[b,l],:]
//      grid (B,4), block 448. emb2->out3 copy issued AFTER the barrier (no sync
//      needed after it) so its latency overlaps the mainloop instead of
//      serializing the fill phase.
__global__ void __launch_bounds__(448, 3) k3(const int* __restrict__ inputs,
                                             const float* __restrict__ emb1,
                                             const float* __restrict__ emb2,
                                             float* __restrict__ out3) {
    int b = blockIdx.x;
    int dt = blockIdx.y * DT;
    __shared__ float xs[L_][DT];          // 51.2 KB
    __shared__ float2 awp[L_][28];        // 22.4 KB
    __shared__ int sidx[L_];
    int t = threadIdx.x;

    if (t < L_) sidx[t] = inputs[b * L_ + t];
    __syncthreads();
    for (int idx = t; idx < L_ * (DT / 4); idx += 448) {
        int l = idx >> 5, q = idx & 31;
        ((float4*)xs[l])[q] = *(const float4*)(emb1 + (size_t)sidx[l] * D_ + dt + q * 4);
    }
    {
        const float4* src = (const float4*)(g_ATTEP + (size_t)b * L_ * 28);
        float4* dst = (float4*)&awp[0][0];
        for (int idx = t; idx < L_ * 28 / 2; idx += 448) dst[idx] = src[idx];
    }
    __syncthreads();

    // emb2 gather -> out3 (post-barrier; nothing in this kernel consumes out3,
    // so no further sync — stalls overlap with the mainloop below).
    {
        float4 tmp[8];
        int cnt = 0;
        int idxs[8];
        for (int idx = t; idx < L_ * (DT / 4); idx += 448) {
            int l = idx >> 5, q = idx & 31;
            tmp[cnt] = *(const float4*)(emb2 + (size_t)sidx[l] * D_ + dt + q * 4);
            idxs[cnt] = idx;
            cnt++;
        }
        for (int i = 0; i < cnt; i++) {
            int l = idxs[i] >> 5, q = idxs[i] & 31;
            *(float4*)(out3 + ((size_t)b * L_ + l) * D_ + dt + q * 4) = tmp[i];
        }
    }

    int lane = t & 31, w = t >> 5;   // w 0..13
    int pg = w % 7;                  // pair group: pairs 4pg..4pg+3
    int jh = w / 7;                  // j half
    int j0 = jh * 64 + lane * 2;
    int p0 = 4 * pg;
    ull acc[4][2];
    #pragma unroll
    for (int k = 0; k < 4; k++) { acc[k][0] = 0ULL; acc[k][1] = 0ULL; }

    #pragma unroll 2
    for (int l = 0; l < L_; l++) {
        float2 xv = *(const float2*)&xs[l][j0];
        ull xx0 = dup2(xv.x), xx1 = dup2(xv.y);
        ulonglong2 wA = *(const ulonglong2*)&awp[l][p0];
        ulonglong2 wB = *(const ulonglong2*)&awp[l][p0 + 2];
        acc[0][0] = fma2(wA.x, xx0, acc[0][0]);
        acc[0][1] = fma2(wA.x, xx1, acc[0][1]);
        acc[1][0] = fma2(wA.y, xx0, acc[1][0]);
        acc[1][1] = fma2(wA.y, xx1, acc[1][1]);
        acc[2][0] = fma2(wB.x, xx0, acc[2][0]);
        acc[2][1] = fma2(wB.x, xx1, acc[2][1]);
        acc[3][0] = fma2(wB.y, xx0, acc[3][0]);
        acc[3][1] = fma2(wB.y, xx1, acc[3][1]);
    }
    #pragma unroll
    for (int k = 0; k < 4; k++) {
        int p = p0 + k;
        if (p < 25) {
            int e0 = 2 * p;
            float2 o0 = make_float2(lo32(acc[k][0]), lo32(acc[k][1]));
            float2 o1 = make_float2(hi32(acc[k][0]), hi32(acc[k][1]));
            *(float2*)(g_EDGE + ((size_t)b * E_ + e0) * D_ + dt + j0) = o0;
            *(float2*)(g_EDGE + ((size_t)b * E_ + e0 + 1) * D_ + dt + j0) = o1;
        }
    }
}

// ---- K4: v[b,e] = edge.w3e; att_node softmax over e, l-pair-packed (pad 56)
__global__ void k4(const int* __restrict__ HT) {
    int b = blockIdx.x;
    int t = threadIdx.x;   // 256
    __shared__ float vsh[E_];
    __shared__ float ush[L_];
    __shared__ float4 wsh[D_ / 4];
    int w = t >> 5, lane = t & 31;
    for (int i = t; i < D_ / 4; i += 256) wsh[i] = ((const float4*)g_w3e)[i];
    if (t < L_) ush[t] = g_U[b * L_ + t];
    for (int idx = t; idx < E_ * (NP - 50); idx += 256) {
        int e = idx / (NP - 50), p = 50 + idx % (NP - 50);
        g_ATTNP[(size_t)b * E_ * NP + e * NP + p] = make_float2(0.f, 0.f);
    }
    __syncthreads();
    for (int e = w; e < E_; e += 8) {
        const float4* er = (const float4*)(g_EDGE + ((size_t)b * E_ + e) * D_);
        float d = 0.f;
        #pragma unroll
        for (int i = 0; i < 4; i++) {
            float4 ev = er[lane + 32 * i];
            float4 wv = wsh[lane + 32 * i];
            d += ev.x * wv.x + ev.y * wv.y + ev.z * wv.z + ev.w * wv.w;
        }
        for (int off = 16; off; off >>= 1) d += __shfl_xor_sync(0xffffffffu, d, off);
        if (lane == 0) vsh[e] = d;
    }
    __syncthreads();

    if (t < L_) {
        int l = t;
        float u = ush[l];
        float vals[E_];
        float mx = -3.4e38f;
        #pragma unroll
        for (int e = 0; e < E_; e++) {
            float s2 = leaky(u + vsh[e]);
            float val = (HT[((size_t)b * E_ + e) * L_ + l] > 0) ? s2 : NEGF;
            vals[e] = val;
            mx = fmaxf(mx, val);
        }
        float sum = 0.f;
        #pragma unroll
        for (int e = 0; e < E_; e++) { vals[e] = expf(vals[e] - mx); sum += vals[e]; }
        float inv = 1.f / sum;
        float* op = (float*)(g_ATTNP + (size_t)b * E_ * NP);
        #pragma unroll
        for (int e = 0; e < E_; e++) op[(e * NP + (l >> 1)) * 2 + (l & 1)] = vals[e] * inv;
    }
}

// ---- K5: node = att_node @ edge + x; write out twice. (R11 exact)
__global__ void __launch_bounds__(448, 2) k5(const int* __restrict__ inputs,
                                             const float* __restrict__ emb1,
                                             float* __restrict__ out) {
    int b = blockIdx.x;
    int dt = blockIdx.y * DT;
    __shared__ float es[E_][DT];          // 25.6 KB
    __shared__ float2 anp[E_][NP];        // 22.4 KB
    __shared__ int sidx[L_];
    int t = threadIdx.x;

    if (t < L_) sidx[t] = inputs[b * L_ + t];
    for (int idx = t; idx < E_ * (DT / 4); idx += 448) {
        int e = idx >> 5, q = idx & 31;
        ((float4*)es[e])[q] = *(const float4*)(g_EDGE + ((size_t)b * E_ + e) * D_ + dt + q * 4);
    }
    {
        const float4* src = (const float4*)(g_ATTNP + (size_t)b * E_ * NP);
        float4* dst = (float4*)&anp[0][0];
        for (int idx = t; idx < E_ * NP / 2; idx += 448) dst[idx] = src[idx];
    }
    __syncthreads();

    int lane = t & 31, w = t >> 5;   // w 0..13
    int pg = w % 7;                  // pairs 8pg..8pg+7 (56 padded pairs exact)
    int jh = w / 7;
    int j0 = jh * 64 + lane * 2;
    int p0 = 8 * pg;
    ull acc[8][2];
    #pragma unroll
    for (int k = 0; k < 8; k++) { acc[k][0] = 0ULL; acc[k][1] = 0ULL; }

    for (int e = 0; e < E_; e++) {
        float2 xv = *(const float2*)&es[e][j0];
        ull xx0 = dup2(xv.x), xx1 = dup2(xv.y);
        ulonglong2 wA = *(const ulonglong2*)&anp[e][p0];
        ulonglong2 wB = *(const ulonglong2*)&anp[e][p0 + 2];
        ulonglong2 wC = *(const ulonglong2*)&anp[e][p0 + 4];
        ulonglong2 wD = *(const ulonglong2*)&anp[e][p0 + 6];
        acc[0][0] = fma2(wA.x, xx0, acc[0][0]);
        acc[0][1] = fma2(wA.x, xx1, acc[0][1]);
        acc[1][0] = fma2(wA.y, xx0, acc[1][0]);
        acc[1][1] = fma2(wA.y, xx1, acc[1][1]);
        acc[2][0] = fma2(wB.x, xx0, acc[2][0]);
        acc[2][1] = fma2(wB.x, xx1, acc[2][1]);
        acc[3][0] = fma2(wB.y, xx0, acc[3][0]);
        acc[3][1] = fma2(wB.y, xx1, acc[3][1]);
        acc[4][0] = fma2(wC.x, xx0, acc[4][0]);
        acc[4][1] = fma2(wC.x, xx1, acc[4][1]);
        acc[5][0] = fma2(wC.y, xx0, acc[5][0]);
        acc[5][1] = fma2(wC.y, xx1, acc[5][1]);
        acc[6][0] = fma2(wD.x, xx0, acc[6][0]);
        acc[6][1] = fma2(wD.x, xx1, acc[6][1]);
        acc[7][0] = fma2(wD.y, xx0, acc[7][0]);
        acc[7][1] = fma2(wD.y, xx1, acc[7][1]);
    }
    #pragma unroll
    for (int k = 0; k < 8; k++) {
        int p = p0 + k;
        if (p < 50) {
            int l0 = 2 * p;
            size_t off0 = ((size_t)b * L_ + l0) * D_ + dt + j0;
            size_t off1 = off0 + D_;
            float2 x0 = *(const float2*)(emb1 + (size_t)sidx[l0] * D_ + dt + j0);
            float2 x1 = *(const float2*)(emb1 + (size_t)sidx[l0 + 1] * D_ + dt + j0);
            float2 o0 = make_float2(lo32(acc[k][0]) + x0.x, lo32(acc[k][1]) + x0.y);
            float2 o1 = make_float2(hi32(acc[k][0]) + x1.x, hi32(acc[k][1]) + x1.y);
            *(float2*)(out + off0) = o0;
            *(float2*)(out + BLD + off0) = o0;
            *(float2*)(out + off1) = o1;
            *(float2*)(out + BLD + off1) = o1;
        }
    }
}

extern "C" void kernel_launch(void* const* d_in, const int* in_sizes, int n_in,
                              void* d_out, int out_size) {
    const int*   inputs = (const int*)d_in[0];
    const int*   HT     = (const int*)d_in[1];
    const float* emb1   = (const float*)d_in[4];
    const float* emb2   = (const float*)d_in[5];
    const float* W2     = (const float*)d_in[6];
    const float* W3     = (const float*)d_in[7];
    const float* ctx    = (const float*)d_in[8];
    const float* a      = (const float*)d_in[9];
    const float* a2     = (const float*)d_in[10];
    float* out = (float*)d_out;

    k0<<<4, 512>>>(W2, W3, ctx, a, a2);
    k1<<<B_ * L_ / 8, 256>>>(inputs, emb1);
    k2<<<B_, 256>>>(HT);
    k3<<<dim3(B_, 4), 448>>>(inputs, emb1, emb2, out + 2 * BLD);
    k4<<<B_, 256>>>(HT);
    k5<<<dim3(B_, 4), 448>>>(inputs, emb1, out);
}

// round 15
// speedup vs baseline: 1.0203x; 1.0203x over previous
#include <cuda_runtime.h>

#define B_ 512
#define L_ 100
#define E_ 50
#define D_ 512
#define DT 128
#define DT5 64         // k5 j-tile
#define NP 56          // padded l-pairs for k5 weights
#define BLD ((size_t)B_ * L_ * D_)
#define NEGF -9000000000000000.0f

typedef unsigned long long ull;

// ---- scratch ----
__device__ float g_EDGE[(size_t)B_ * E_ * D_];     // edge feats (52 MB)
__device__ float2 g_ATTEP[(size_t)B_ * L_ * 28];   // att_edge, e-pair packed [b][l][pair]
__device__ float2 g_ATTNP[(size_t)B_ * E_ * NP];   // att_node, l-pair packed [b][e][pair]
__device__ float g_S[B_ * L_];                     // leaky(c0 + x.w_an)
__device__ float g_U[B_ * L_];                     // x.w_a2n
__device__ float g_wan[D_], g_wa2n[D_], g_w3e[D_];
__device__ float g_c0;

__device__ __forceinline__ float leaky(float x) { return x >= 0.f ? x : 0.2f * x; }

__device__ __forceinline__ ull fma2(ull a, ull b, ull c) {
    ull d;
    asm("fma.rn.f32x2 %0, %1, %2, %3;" : "=l"(d) : "l"(a), "l"(b), "l"(c));
    return d;
}
__device__ __forceinline__ ull dup2(float x) {
    ull d;
    asm("mov.b64 %0, {%1, %1};" : "=l"(d) : "f"(x));
    return d;
}
__device__ __forceinline__ float lo32(ull v) { return ((float2*)&v)->x; }
__device__ __forceinline__ float hi32(ull v) { return ((float2*)&v)->y; }

// ---- K0: fold W2/W3 into vectors (coalesced warp-per-row)
__global__ void k0(const float* __restrict__ W2, const float* __restrict__ W3,
                   const float* __restrict__ ctx, const float* __restrict__ a,
                   const float* __restrict__ a2) {
    int which = blockIdx.x;   // 4 blocks, 512 threads
    int t = threadIdx.x;
    if (which < 3) {
        const float* M = (which == 2) ? W3 : W2;
        const float* vec = (which == 0) ? (a + D_) : (which == 1 ? a2 : (a2 + D_));
        float* dst = (which == 0) ? g_wan : (which == 1 ? g_wa2n : g_w3e);
        __shared__ float vs[D_];
        vs[t] = vec[t];
        __syncthreads();
        int w = t >> 5, lane = t & 31;   // 16 warps
        for (int d = w; d < D_; d += 16) {
            const float4* row = (const float4*)(M + (size_t)d * D_);
            float s = 0.f;
            #pragma unroll
            for (int i = 0; i < 4; i++) {
                float4 mv = row[lane + 32 * i];
                float4 vv = *(const float4*)&vs[(lane + 32 * i) * 4];
                s += mv.x * vv.x + mv.y * vv.y + mv.z * vv.z + mv.w * vv.w;
            }
            for (int off = 16; off; off >>= 1) s += __shfl_xor_sync(0xffffffffu, s, off);
            if (lane == 0) dst[d] = s;
        }
    } else {
        __shared__ float sh[512];
        sh[t] = ctx[t] * a[t];
        __syncthreads();
        for (int o = 256; o > 0; o >>= 1) { if (t < o) sh[t] += sh[t + o]; __syncthreads(); }
        if (t == 0) g_c0 = sh[0];
    }
}

// ---- K1: warp-per-row dots from emb1 -> g_S, g_U
__global__ void k1(const int* __restrict__ inputs, const float* __restrict__ emb1) {
    int w = threadIdx.x >> 5, lane = threadIdx.x & 31;
    int bl = blockIdx.x * 8 + w;               // grid 6400 x 8 warps = 51200 rows
    size_t nid = (size_t)inputs[bl];
    const float4* r1 = (const float4*)(emb1 + nid * D_);

    float dan = 0.f, da2 = 0.f;
    #pragma unroll
    for (int i = 0; i < 4; i++) {
        int idx = lane + 32 * i;
        float4 v = r1[idx];
        float4 wa = ((const float4*)g_wan)[idx];
        float4 wb = ((const float4*)g_wa2n)[idx];
        dan += v.x * wa.x + v.y * wa.y + v.z * wa.z + v.w * wa.w;
        da2 += v.x * wb.x + v.y * wb.y + v.z * wb.z + v.w * wb.w;
    }
    for (int off = 16; off; off >>= 1) {
        dan += __shfl_xor_sync(0xffffffffu, dan, off);
        da2 += __shfl_xor_sync(0xffffffffu, da2, off);
    }
    if (lane == 0) {
        g_S[bl] = leaky(g_c0 + dan);
        g_U[bl] = da2;
    }
}

// ---- K2: att_edge softmax over l, written e-pair-packed: ATTEP[b][l][e>>1].{x,y}
__global__ void k2(const int* __restrict__ HT) {
    int b = blockIdx.x;
    __shared__ float s[L_];
    int t = threadIdx.x;   // 256
    if (t < L_) s[t] = g_S[b * L_ + t];
    for (int idx = t; idx < L_ * 3; idx += 256) {
        int l = idx / 3, p = 25 + idx % 3;
        g_ATTEP[(size_t)b * L_ * 28 + l * 28 + p] = make_float2(0.f, 0.f);
    }
    __syncthreads();
    float* op = (float*)(g_ATTEP + (size_t)b * L_ * 28);
    int w = t >> 5, lane = t & 31;
    for (int e = w; e < E_; e += 8) {
        const int* m = HT + ((size_t)b * E_ + e) * L_;
        float vals[4];
        float mx = -3.4e38f;
        #pragma unroll
        for (int k = 0; k < 4; k++) {
            int l = lane + 32 * k;
            float v = -3.4e38f;
            if (l < L_) v = (m[l] > 0) ? s[l] : NEGF;
            vals[k] = v;
            mx = fmaxf(mx, v);
        }
        for (int off = 16; off; off >>= 1) mx = fmaxf(mx, __shfl_xor_sync(0xffffffffu, mx, off));
        float sum = 0.f;
        #pragma unroll
        for (int k = 0; k < 4; k++) {
            int l = lane + 32 * k;
            float ev = 0.f;
            if (l < L_) ev = expf(vals[k] - mx);
            vals[k] = ev;
            sum += ev;
        }
        for (int off = 16; off; off >>= 1) sum += __shfl_xor_sync(0xffffffffu, sum, off);
        float inv = 1.f / sum;
        #pragma unroll
        for (int k = 0; k < 4; k++) {
            int l = lane + 32 * k;
            if (l < L_) op[(l * 28 + (e >> 1)) * 2 + (e & 1)] = vals[k] * inv;
        }
    }
}

// ---- K3: edge[b,e,:] = sum_l attE[b,e,l] * emb1[inputs[b,l],:]
//      grid (B,4), block 448. Single barrier (direct cached inputs[] loads);
//      emb2 copy loads prefetched before xs fill, stores after barrier.
__global__ void __launch_bounds__(448, 3) k3(const int* __restrict__ inputs,
                                             const float* __restrict__ emb1,
                                             const float* __restrict__ emb2,
                                             float* __restrict__ out3) {
    int b = blockIdx.x;
    int dt = blockIdx.y * DT;
    __shared__ float xs[L_][DT];          // 51.2 KB
    __shared__ float2 awp[L_][28];        // 22.4 KB
    int t = threadIdx.x;
    const int* binp = inputs + b * L_;

    // prefetch emb2 copy loads (independent of barrier)
    float4 tmp[8];
    int cnt = 0;
    for (int idx = t; idx < L_ * (DT / 4); idx += 448) {
        int l = idx >> 5, q = idx & 31;
        tmp[cnt++] = *(const float4*)(emb2 + (size_t)__ldg(&binp[l]) * D_ + dt + q * 4);
    }
    for (int idx = t; idx < L_ * (DT / 4); idx += 448) {
        int l = idx >> 5, q = idx & 31;
        ((float4*)xs[l])[q] = *(const float4*)(emb1 + (size_t)__ldg(&binp[l]) * D_ + dt + q * 4);
    }
    {
        const float4* src = (const float4*)(g_ATTEP + (size_t)b * L_ * 28);
        float4* dst = (float4*)&awp[0][0];
        for (int idx = t; idx < L_ * 28 / 2; idx += 448) dst[idx] = src[idx];
    }
    __syncthreads();

    // emb2 -> out3 stores (no sync needed after; overlaps mainloop)
    {
        int i = 0;
        for (int idx = t; idx < L_ * (DT / 4); idx += 448) {
            int l = idx >> 5, q = idx & 31;
            *(float4*)(out3 + ((size_t)b * L_ + l) * D_ + dt + q * 4) = tmp[i++];
        }
    }

    int lane = t & 31, w = t >> 5;   // w 0..13
    int pg = w % 7;                  // pair group: pairs 4pg..4pg+3
    int jh = w / 7;                  // j half
    int j0 = jh * 64 + lane * 2;
    int p0 = 4 * pg;
    ull acc[4][2];
    #pragma unroll
    for (int k = 0; k < 4; k++) { acc[k][0] = 0ULL; acc[k][1] = 0ULL; }

    #pragma unroll 2
    for (int l = 0; l < L_; l++) {
        float2 xv = *(const float2*)&xs[l][j0];
        ull xx0 = dup2(xv.x), xx1 = dup2(xv.y);
        ulonglong2 wA = *(const ulonglong2*)&awp[l][p0];
        ulonglong2 wB = *(const ulonglong2*)&awp[l][p0 + 2];
        acc[0][0] = fma2(wA.x, xx0, acc[0][0]);
        acc[0][1] = fma2(wA.x, xx1, acc[0][1]);
        acc[1][0] = fma2(wA.y, xx0, acc[1][0]);
        acc[1][1] = fma2(wA.y, xx1, acc[1][1]);
        acc[2][0] = fma2(wB.x, xx0, acc[2][0]);
        acc[2][1] = fma2(wB.x, xx1, acc[2][1]);
        acc[3][0] = fma2(wB.y, xx0, acc[3][0]);
        acc[3][1] = fma2(wB.y, xx1, acc[3][1]);
    }
    #pragma unroll
    for (int k = 0; k < 4; k++) {
        int p = p0 + k;
        if (p < 25) {
            int e0 = 2 * p;
            float2 o0 = make_float2(lo32(acc[k][0]), lo32(acc[k][1]));
            float2 o1 = make_float2(hi32(acc[k][0]), hi32(acc[k][1]));
            *(float2*)(g_EDGE + ((size_t)b * E_ + e0) * D_ + dt + j0) = o0;
            *(float2*)(g_EDGE + ((size_t)b * E_ + e0 + 1) * D_ + dt + j0) = o1;
        }
    }
}

// ---- K4: v[b,e] = edge.w3e; att_node softmax over e, l-pair-packed (pad 56)
__global__ void k4(const int* __restrict__ HT) {
    int b = blockIdx.x;
    int t = threadIdx.x;   // 256
    __shared__ float vsh[E_];
    __shared__ float ush[L_];
    __shared__ float4 wsh[D_ / 4];
    int w = t >> 5, lane = t & 31;
    for (int i = t; i < D_ / 4; i += 256) wsh[i] = ((const float4*)g_w3e)[i];
    if (t < L_) ush[t] = g_U[b * L_ + t];
    for (int idx = t; idx < E_ * (NP - 50); idx += 256) {
        int e = idx / (NP - 50), p = 50 + idx % (NP - 50);
        g_ATTNP[(size_t)b * E_ * NP + e * NP + p] = make_float2(0.f, 0.f);
    }
    __syncthreads();
    for (int e = w; e < E_; e += 8) {
        const float4* er = (const float4*)(g_EDGE + ((size_t)b * E_ + e) * D_);
        float d = 0.f;
        #pragma unroll
        for (int i = 0; i < 4; i++) {
            float4 ev = er[lane + 32 * i];
            float4 wv = wsh[lane + 32 * i];
            d += ev.x * wv.x + ev.y * wv.y + ev.z * wv.z + ev.w * wv.w;
        }
        for (int off = 16; off; off >>= 1) d += __shfl_xor_sync(0xffffffffu, d, off);
        if (lane == 0) vsh[e] = d;
    }
    __syncthreads();

    if (t < L_) {
        int l = t;
        float u = ush[l];
        float vals[E_];
        float mx = -3.4e38f;
        #pragma unroll
        for (int e = 0; e < E_; e++) {
            float s2 = leaky(u + vsh[e]);
            float val = (HT[((size_t)b * E_ + e) * L_ + l] > 0) ? s2 : NEGF;
            vals[e] = val;
            mx = fmaxf(mx, val);
        }
        float sum = 0.f;
        #pragma unroll
        for (int e = 0; e < E_; e++) { vals[e] = expf(vals[e] - mx); sum += vals[e]; }
        float inv = 1.f / sum;
        float* op = (float*)(g_ATTNP + (size_t)b * E_ * NP);
        #pragma unroll
        for (int e = 0; e < E_; e++) op[(e * NP + (l >> 1)) * 2 + (l & 1)] = vals[e] * inv;
    }
}

// ---- K5: node = att_node @ edge + x; write out twice.
//      grid (B,8) with 64-wide j-tiles, block 448 = 14 warps x P=4 pairs (56 exact).
//      Small tile -> smem 35 KB, acc 8 ull -> occupancy 4 CTAs = 56 warps/SM.
__global__ void __launch_bounds__(448, 4) k5(const int* __restrict__ inputs,
                                             const float* __restrict__ emb1,
                                             float* __restrict__ out) {
    int b = blockIdx.x;
    int dt = blockIdx.y * DT5;
    __shared__ float es[E_][DT5];         // 12.8 KB
    __shared__ float2 anp[E_][NP];        // 22.4 KB
    __shared__ int sidx[L_];
    int t = threadIdx.x;

    if (t < L_) sidx[t] = inputs[b * L_ + t];
    for (int idx = t; idx < E_ * (DT5 / 4); idx += 448) {
        int e = idx >> 4, q = idx & 15;
        ((float4*)es[e])[q] = *(const float4*)(g_EDGE + ((size_t)b * E_ + e) * D_ + dt + q * 4);
    }
    {
        const float4* src = (const float4*)(g_ATTNP + (size_t)b * E_ * NP);
        float4* dst = (float4*)&anp[0][0];
        for (int idx = t; idx < E_ * NP / 2; idx += 448) dst[idx] = src[idx];
    }
    __syncthreads();

    int lane = t & 31, w = t >> 5;   // w 0..13
    int j0 = lane * 2;               // covers 64 floats
    int p0 = 4 * w;                  // pairs p0..p0+3 (56 exact)
    ull acc[4][2];
    #pragma unroll
    for (int k = 0; k < 4; k++) { acc[k][0] = 0ULL; acc[k][1] = 0ULL; }

    #pragma unroll 2
    for (int e = 0; e < E_; e++) {
        float2 xv = *(const float2*)&es[e][j0];
        ull xx0 = dup2(xv.x), xx1 = dup2(xv.y);
        ulonglong2 wA = *(const ulonglong2*)&anp[e][p0];
        ulonglong2 wB = *(const ulonglong2*)&anp[e][p0 + 2];
        acc[0][0] = fma2(wA.x, xx0, acc[0][0]);
        acc[0][1] = fma2(wA.x, xx1, acc[0][1]);
        acc[1][0] = fma2(wA.y, xx0, acc[1][0]);
        acc[1][1] = fma2(wA.y, xx1, acc[1][1]);
        acc[2][0] = fma2(wB.x, xx0, acc[2][0]);
        acc[2][1] = fma2(wB.x, xx1, acc[2][1]);
        acc[3][0] = fma2(wB.y, xx0, acc[3][0]);
        acc[3][1] = fma2(wB.y, xx1, acc[3][1]);
    }
    #pragma unroll
    for (int k = 0; k < 4; k++) {
        int p = p0 + k;
        if (p < 50) {
            int l0 = 2 * p;
            size_t off0 = ((size_t)b * L_ + l0) * D_ + dt + j0;
            size_t off1 = off0 + D_;
            float2 x0 = *(const float2*)(emb1 + (size_t)sidx[l0] * D_ + dt + j0);
            float2 x1 = *(const float2*)(emb1 + (size_t)sidx[l0 + 1] * D_ + dt + j0);
            float2 o0 = make_float2(lo32(acc[k][0]) + x0.x, lo32(acc[k][1]) + x0.y);
            float2 o1 = make_float2(hi32(acc[k][0]) + x1.x, hi32(acc[k][1]) + x1.y);
            *(float2*)(out + off0) = o0;
            *(float2*)(out + BLD + off0) = o0;
            *(float2*)(out + off1) = o1;
            *(float2*)(out + BLD + off1) = o1;
        }
    }
}

extern "C" void kernel_launch(void* const* d_in, const int* in_sizes, int n_in,
                              void* d_out, int out_size) {
    const int*   inputs = (const int*)d_in[0];
    const int*   HT     = (const int*)d_in[1];
    const float* emb1   = (const float*)d_in[4];
    const float* emb2   = (const float*)d_in[5];
    const float* W2     = (const float*)d_in[6];
    const float* W3     = (const float*)d_in[7];
    const float* ctx    = (const float*)d_in[8];
    const float* a      = (const float*)d_in[9];
    const float* a2     = (const float*)d_in[10];
    float* out = (float*)d_out;

    k0<<<4, 512>>>(W2, W3, ctx, a, a2);
    k1<<<B_ * L_ / 8, 256>>>(inputs, emb1);
    k2<<<B_, 256>>>(HT);
    k3<<<dim3(B_, 4), 448>>>(inputs, emb1, emb2, out + 2 * BLD);
    k4<<<B_, 256>>>(HT);
    k5<<<dim3(B_, 8), 448>>>(inputs, emb1, out);
}